// round 2
// baseline (speedup 1.0000x reference)
#include <cuda_runtime.h>

// Problem constants
#define BB   4
#define NPTS 16384
#define SPTS 4096
#define C1   128
#define C2   256
#define CIN  384
#define H1   256
#define H2   128

// ---------------- device scratch (no allocations allowed) ----------------
__device__ float g_W1t[CIN * H1];   // [k][o]  BN-folded, transposed
__device__ float g_W2t[H1 * H2];    // [k][o]
__device__ float g_b1f[H1];
__device__ float g_b2f[H2];
__device__ int   g_ni[BB * NPTS * 3];
__device__ float g_nw[BB * NPTS * 3];

// ---------------- packed f32x2 helpers ----------------
__device__ __forceinline__ unsigned long long pk2(float lo, float hi) {
    unsigned long long r;
    asm("mov.b64 %0, {%1, %2};" : "=l"(r) : "f"(lo), "f"(hi));
    return r;
}
__device__ __forceinline__ float2 upk(unsigned long long v) {
    float2 r;
    asm("mov.b64 {%0, %1}, %2;" : "=f"(r.x), "=f"(r.y) : "l"(v));
    return r;
}
__device__ __forceinline__ void fma2(unsigned long long& d,
                                     unsigned long long a,
                                     unsigned long long b) {
#if defined(__CUDA_ARCH__) && (__CUDA_ARCH__ >= 1000)
    asm("fma.rn.f32x2 %0, %1, %2, %0;" : "+l"(d) : "l"(a), "l"(b));
#else
    float2 df = upk(d), af = upk(a), bf = upk(b);
    df.x = fmaf(af.x, bf.x, df.x);
    df.y = fmaf(af.y, bf.y, df.y);
    d = pk2(df.x, df.y);
#endif
}

// ---------------- kernel A: fold BN into weights, transpose ----------------
__global__ void prep_kernel(const float* __restrict__ W1, const float* __restrict__ b1,
                            const float* __restrict__ g1, const float* __restrict__ be1,
                            const float* __restrict__ m1, const float* __restrict__ v1,
                            const float* __restrict__ W2, const float* __restrict__ b2,
                            const float* __restrict__ g2, const float* __restrict__ be2,
                            const float* __restrict__ m2, const float* __restrict__ v2) {
    int idx = blockIdx.x * blockDim.x + threadIdx.x;
    int stride = gridDim.x * blockDim.x;
    for (int i = idx; i < CIN * H1; i += stride) {
        int k = i >> 8, o = i & 255;
        float a = g1[o] * rsqrtf(v1[o] + 1e-5f);
        g_W1t[k * H1 + o] = W1[o * CIN + k] * a;
    }
    for (int i = idx; i < H1 * H2; i += stride) {
        int k = i >> 7, o = i & 127;
        float a = g2[o] * rsqrtf(v2[o] + 1e-5f);
        g_W2t[k * H2 + o] = W2[o * H1 + k] * a;
    }
    for (int o = idx; o < H1; o += stride) {
        float a = g1[o] * rsqrtf(v1[o] + 1e-5f);
        g_b1f[o] = (b1[o] - m1[o]) * a + be1[o];
    }
    for (int o = idx; o < H2; o += stride) {
        float a = g2[o] * rsqrtf(v2[o] + 1e-5f);
        g_b2f[o] = (b2[o] - m2[o]) * a + be2[o];
    }
}

// ---------------- kernel B: exact 3-NN + interpolation weights ----------------
__global__ void __launch_bounds__(256) nn_kernel(const float* __restrict__ xyz1,
                                                 const float* __restrict__ xyz2) {
    extern __shared__ float4 sc[];   // SPTS entries: (|c|^2, -2cx, -2cy, -2cz)
    const int b = blockIdx.y;
    const int n = blockIdx.x * 256 + threadIdx.x;

    const float* x2 = xyz2 + b * SPTS * 3;
    for (int s = threadIdx.x; s < SPTS; s += 256) {
        float x = x2[s * 3 + 0], y = x2[s * 3 + 1], z = x2[s * 3 + 2];
        sc[s] = make_float4(fmaf(x, x, fmaf(y, y, z * z)), -2.f * x, -2.f * y, -2.f * z);
    }
    __syncthreads();

    const float* q = xyz1 + (b * NPTS + n) * 3;
    const float qx = q[0], qy = q[1], qz = q[2];

    const float INF = __int_as_float(0x7f800000);
    float d0 = INF, d1 = INF, d2 = INF;
    int i0 = 0, i1 = 0, i2 = 0;

#pragma unroll 4
    for (int s = 0; s < SPTS; s++) {
        float4 c = sc[s];
        float t = fmaf(c.y, qx, c.x);
        t = fmaf(c.z, qy, t);
        t = fmaf(c.w, qz, t);
        // t = |c|^2 - 2 q.c ; ranking identical to full distance for fixed q
        if (t < d2) {
            if (t < d1) {
                d2 = d1; i2 = i1;
                if (t < d0) { d1 = d0; i1 = i0; d0 = t; i0 = s; }
                else        { d1 = t;  i1 = s; }
            } else { d2 = t; i2 = s; }
        }
    }

    const float qn = fmaf(qx, qx, fmaf(qy, qy, qz * qz));
    float r0 = 1.f / ((d0 + qn) + 1e-8f);
    float r1 = 1.f / ((d1 + qn) + 1e-8f);
    float r2 = 1.f / ((d2 + qn) + 1e-8f);
    float inv = 1.f / (r0 + r1 + r2);

    const int base = (b * NPTS + n) * 3;
    g_ni[base + 0] = i0; g_ni[base + 1] = i1; g_ni[base + 2] = i2;
    g_nw[base + 0] = r0 * inv; g_nw[base + 1] = r1 * inv; g_nw[base + 2] = r2 * inv;
}

// ---------------- kernel C: fused interp + MLP(384->256->128) ----------------
// Block: 256 threads, 64 points. SMEM:
//   xs [384][68]   (104448 B)  concat input, [k][p] layout (stride 68: pad + 16B align)
//   r2 [max(256*68, 2*32*256)] (69632 B)   hidden h1 OR W1 tile(normal+swapped)
// GEMM2 weight tiles reuse the xs region.
#define XST 68
#define SMEM_C_FLOATS (CIN * XST + H1 * XST)
#define SMEM_C_BYTES  (SMEM_C_FLOATS * 4)

__global__ void __launch_bounds__(256, 1) fused_kernel(const float* __restrict__ feat1,
                                                       const float* __restrict__ feat2,
                                                       float* __restrict__ out) {
    extern __shared__ float sm[];
    float* xs   = sm;                 // [CIN][XST]
    float* r2   = sm + CIN * XST;
    float* wt_n = r2;                 // [32][H1]
    float* wt_s = r2 + 32 * H1;       // [32][H1] pair-swapped
    float* hs   = r2;                 // [H1][XST] (after GEMM1)
    float* w2n  = sm;                 // GEMM2 tiles live in xs region
    float* w2s  = sm + 32 * H2;

    const int tid = threadIdx.x;
    const int b   = blockIdx.y;
    const int n0  = blockIdx.x * 64;

    // ---- phase 1a: feat1 -> xs rows [0,128), transposed ----
    {
        const float* f1 = feat1 + (b * NPTS + n0) * C1;
#pragma unroll
        for (int it = 0; it < 8; it++) {
            int i = tid + it * 256;
            int k = i & 127, pq = i >> 7;          // pq in [0,16): 4 points each
            const float* src = f1 + pq * 4 * C1 + k;
            float4 v;
            v.x = src[0]; v.y = src[C1]; v.z = src[2 * C1]; v.w = src[3 * C1];
            *(float4*)(xs + k * XST + pq * 4) = v;
        }
    }
    // ---- phase 1b: 3-NN interpolation -> xs rows [128,384) ----
    {
        const int p  = tid >> 2;       // 0..63
        const int cq = tid & 3;        // 4 threads per point, 64 channels each
        const int base = (b * NPTS + n0 + p) * 3;
        const int j0 = g_ni[base], j1 = g_ni[base + 1], j2 = g_ni[base + 2];
        const float w0 = g_nw[base], w1 = g_nw[base + 1], w2 = g_nw[base + 2];
        const float4* f2 = (const float4*)(feat2 + b * SPTS * C2);
        const float4* r0p = f2 + j0 * (C2 / 4);
        const float4* r1p = f2 + j1 * (C2 / 4);
        const float4* r2p = f2 + j2 * (C2 / 4);
#pragma unroll 4
        for (int t = 0; t < 16; t++) {
            int c4 = cq * 16 + t;
            float4 a = __ldg(r0p + c4), bb = __ldg(r1p + c4), cc = __ldg(r2p + c4);
            float rx = fmaf(w0, a.x, fmaf(w1, bb.x, w2 * cc.x));
            float ry = fmaf(w0, a.y, fmaf(w1, bb.y, w2 * cc.y));
            float rz = fmaf(w0, a.z, fmaf(w1, bb.z, w2 * cc.z));
            float rw = fmaf(w0, a.w, fmaf(w1, bb.w, w2 * cc.w));
            float* dst = xs + (C1 + c4 * 4) * XST + p;
            dst[0] = rx; dst[XST] = ry; dst[2 * XST] = rz; dst[3 * XST] = rw;
        }
    }

    const int p0 = (tid & 7) * 8;      // 8 points
    const int c0 = (tid >> 3) * 8;     // 8 channels (GEMM1)

    // ---- GEMM1: xs[384][64] x W1t -> h1[256][64], diag-paired f32x2 ----
    unsigned long long accA[4][4], accB[4][4];
#pragma unroll
    for (int j = 0; j < 4; j++) {
        float lo = g_b1f[c0 + 2 * j], hi = g_b1f[c0 + 2 * j + 1];
        unsigned long long bn = pk2(lo, hi), bs = pk2(hi, lo);
#pragma unroll
        for (int qq = 0; qq < 4; qq++) { accA[qq][j] = bn; accB[qq][j] = bs; }
    }

    for (int kt = 0; kt < CIN; kt += 32) {
        __syncthreads();               // prior tile reads / phase1 done
        const float* wg = g_W1t + kt * H1;
#pragma unroll
        for (int it = 0; it < 32; it++) {
            int i = tid + it * 256;
            int kk = i >> 8, o = i & 255;
            float v = wg[i];
            wt_n[i] = v;
            wt_s[kk * H1 + (o ^ 1)] = v;
        }
        __syncthreads();
#pragma unroll 8
        for (int kk = 0; kk < 32; kk++) {
            const float* xr = xs + (kt + kk) * XST + p0;
            ulonglong2 xa = *(const ulonglong2*)xr;
            ulonglong2 xb = *(const ulonglong2*)(xr + 4);
            const float* wr  = wt_n + kk * H1 + c0;
            const float* wsr = wt_s + kk * H1 + c0;
            ulonglong2 wa = *(const ulonglong2*)wr;
            ulonglong2 wb = *(const ulonglong2*)(wr + 4);
            ulonglong2 sa = *(const ulonglong2*)wsr;
            ulonglong2 sb = *(const ulonglong2*)(wsr + 4);
            unsigned long long xp[4] = {xa.x, xa.y, xb.x, xb.y};
            unsigned long long wn[4] = {wa.x, wa.y, wb.x, wb.y};
            unsigned long long ws[4] = {sa.x, sa.y, sb.x, sb.y};
#pragma unroll
            for (int qq = 0; qq < 4; qq++)
#pragma unroll
                for (int j = 0; j < 4; j++) {
                    fma2(accA[qq][j], xp[qq], wn[j]);
                    fma2(accB[qq][j], xp[qq], ws[j]);
                }
        }
    }
    __syncthreads();                   // tile reads done before hs overwrite

    // ---- epilogue 1: bias already folded in; ReLU; write h1 to hs[c][p] ----
#pragma unroll
    for (int qq = 0; qq < 4; qq++)
#pragma unroll
        for (int j = 0; j < 4; j++) {
            float2 a = upk(accA[qq][j]), bb = upk(accB[qq][j]);
            hs[(c0 + 2 * j)     * XST + p0 + 2 * qq]     = fmaxf(a.x, 0.f);
            hs[(c0 + 2 * j + 1) * XST + p0 + 2 * qq]     = fmaxf(bb.x, 0.f);
            hs[(c0 + 2 * j)     * XST + p0 + 2 * qq + 1] = fmaxf(bb.y, 0.f);
            hs[(c0 + 2 * j + 1) * XST + p0 + 2 * qq + 1] = fmaxf(a.y, 0.f);
        }

    // ---- GEMM2: hs[256][64] x W2t -> out[128][64] ----
    const int d0c = (tid >> 3) * 4;    // 4 channels
    unsigned long long a2A[4][2], a2B[4][2];
#pragma unroll
    for (int j = 0; j < 2; j++) {
        float lo = g_b2f[d0c + 2 * j], hi = g_b2f[d0c + 2 * j + 1];
        unsigned long long bn = pk2(lo, hi), bs = pk2(hi, lo);
#pragma unroll
        for (int qq = 0; qq < 4; qq++) { a2A[qq][j] = bn; a2B[qq][j] = bs; }
    }

    for (int kt = 0; kt < H1; kt += 32) {
        __syncthreads();               // hs writes done (iter 0) / prior tile reads done
        const float* wg = g_W2t + kt * H2;
#pragma unroll
        for (int it = 0; it < 16; it++) {
            int i = tid + it * 256;
            int kk = i >> 7, o = i & 127;
            float v = wg[i];
            w2n[i] = v;
            w2s[kk * H2 + (o ^ 1)] = v;
        }
        __syncthreads();
#pragma unroll 8
        for (int kk = 0; kk < 32; kk++) {
            const float* xr = hs + (kt + kk) * XST + p0;
            ulonglong2 xa = *(const ulonglong2*)xr;
            ulonglong2 xb = *(const ulonglong2*)(xr + 4);
            ulonglong2 wa = *(const ulonglong2*)(w2n + kk * H2 + d0c);
            ulonglong2 sa = *(const ulonglong2*)(w2s + kk * H2 + d0c);
            unsigned long long xp[4] = {xa.x, xa.y, xb.x, xb.y};
            unsigned long long wn[2] = {wa.x, wa.y};
            unsigned long long ws[2] = {sa.x, sa.y};
#pragma unroll
            for (int qq = 0; qq < 4; qq++)
#pragma unroll
                for (int j = 0; j < 2; j++) {
                    fma2(a2A[qq][j], xp[qq], wn[j]);
                    fma2(a2B[qq][j], xp[qq], ws[j]);
                }
        }
    }

    // ---- epilogue 2: ReLU, store fp32 output ----
    float* op = out + (b * NPTS + n0 + p0) * H2 + d0c;
#pragma unroll
    for (int qq = 0; qq < 4; qq++) {
        float2 a0 = upk(a2A[qq][0]), a1 = upk(a2A[qq][1]);
        float2 b0 = upk(a2B[qq][0]), b1 = upk(a2B[qq][1]);
        float4 v0 = make_float4(fmaxf(a0.x, 0.f), fmaxf(b0.x, 0.f),
                                fmaxf(a1.x, 0.f), fmaxf(b1.x, 0.f));
        float4 v1 = make_float4(fmaxf(b0.y, 0.f), fmaxf(a0.y, 0.f),
                                fmaxf(b1.y, 0.f), fmaxf(a1.y, 0.f));
        *(float4*)(op + (2 * qq)     * H2) = v0;
        *(float4*)(op + (2 * qq + 1) * H2) = v1;
    }
}

// ---------------- launch ----------------
extern "C" void kernel_launch(void* const* d_in, const int* in_sizes, int n_in,
                              void* d_out, int out_size) {
    const float* xyz1  = (const float*)d_in[0];
    const float* feat1 = (const float*)d_in[1];
    const float* xyz2  = (const float*)d_in[2];
    const float* feat2 = (const float*)d_in[3];
    const float* W1  = (const float*)d_in[4];
    const float* b1  = (const float*)d_in[5];
    const float* g1  = (const float*)d_in[6];
    const float* be1 = (const float*)d_in[7];
    const float* m1  = (const float*)d_in[8];
    const float* v1  = (const float*)d_in[9];
    const float* W2  = (const float*)d_in[10];
    const float* b2  = (const float*)d_in[11];
    const float* g2  = (const float*)d_in[12];
    const float* be2 = (const float*)d_in[13];
    const float* m2  = (const float*)d_in[14];
    const float* v2  = (const float*)d_in[15];
    float* out = (float*)d_out;

    cudaFuncSetAttribute(nn_kernel, cudaFuncAttributeMaxDynamicSharedMemorySize,
                         SPTS * (int)sizeof(float4));
    cudaFuncSetAttribute(fused_kernel, cudaFuncAttributeMaxDynamicSharedMemorySize,
                         SMEM_C_BYTES);

    prep_kernel<<<128, 256>>>(W1, b1, g1, be1, m1, v1, W2, b2, g2, be2, m2, v2);
    nn_kernel<<<dim3(NPTS / 256, BB), 256, SPTS * sizeof(float4)>>>(xyz1, xyz2);
    fused_kernel<<<dim3(NPTS / 64, BB), 256, SMEM_C_BYTES>>>(feat1, feat2, out);
}

// round 5
// speedup vs baseline: 2.0908x; 2.0908x over previous
#include <cuda_runtime.h>
#include <cuda_bf16.h>
#include <cstdint>

// Problem constants
#define BB   4
#define NPTS 16384
#define SPTS 4096
#define C1   128
#define C2   256
#define CIN  384
#define H1   256
#define H2   128

// SMEM row strides (bf16 elements): 72*2=144B and 264*2=528B, both ≡16 mod 128
// -> conflict-free ldmatrix across 8 rows.
#define A1S  72
#define H1S  264

// W1: 6 k-chunks of [256 n][72 k] bf16 = 36864 B each (hi and lo separately)
// W2: 4 k-chunks of [128 n][72 k] bf16 = 18432 B each
#define W1CH 36864
#define W2CH 18432

__device__ __align__(16) unsigned char g_W1h[6 * W1CH];
__device__ __align__(16) unsigned char g_W1l[6 * W1CH];
__device__ __align__(16) unsigned char g_W2h[4 * W2CH];
__device__ __align__(16) unsigned char g_W2l[4 * W2CH];
__device__ float g_b1f[H1];
__device__ float g_b2f[H2];
__device__ int   g_ni[BB * NPTS * 3];
__device__ float g_nw[BB * NPTS * 3];

// ---------------- helpers ----------------
__device__ __forceinline__ uint32_t smem_to_u32(const void* p) {
    uint32_t a;
    asm("{ .reg .u64 t; cvta.to.shared.u64 t, %1; cvt.u32.u64 %0, t; }" : "=r"(a) : "l"(p));
    return a;
}
__device__ __forceinline__ void ldsm4(uint32_t* r, uint32_t a) {
    asm volatile("ldmatrix.sync.aligned.m8n8.x4.shared.b16 {%0,%1,%2,%3}, [%4];"
                 : "=r"(r[0]), "=r"(r[1]), "=r"(r[2]), "=r"(r[3]) : "r"(a));
}
__device__ __forceinline__ void mma_bf16(float* d, const uint32_t* a, const uint32_t* b) {
    asm volatile("mma.sync.aligned.m16n8k16.row.col.f32.bf16.bf16.f32 "
                 "{%0,%1,%2,%3}, {%4,%5,%6,%7}, {%8,%9}, {%0,%1,%2,%3};"
                 : "+f"(d[0]), "+f"(d[1]), "+f"(d[2]), "+f"(d[3])
                 : "r"(a[0]), "r"(a[1]), "r"(a[2]), "r"(a[3]), "r"(b[0]), "r"(b[1]));
}

__device__ __forceinline__ void pack_split8(const float* v, uint4& H, uint4& L) {
    unsigned int h[4], l[4];
#pragma unroll
    for (int j = 0; j < 4; j++) {
        __nv_bfloat16 h0 = __float2bfloat16(v[2 * j]);
        __nv_bfloat16 h1 = __float2bfloat16(v[2 * j + 1]);
        float l0 = v[2 * j]     - __bfloat162float(h0);
        float l1 = v[2 * j + 1] - __bfloat162float(h1);
        h[j] = (unsigned int)__bfloat16_as_ushort(h0) |
               ((unsigned int)__bfloat16_as_ushort(h1) << 16);
        l[j] = (unsigned int)__bfloat16_as_ushort(__float2bfloat16(l0)) |
               ((unsigned int)__bfloat16_as_ushort(__float2bfloat16(l1)) << 16);
    }
    H = make_uint4(h[0], h[1], h[2], h[3]);
    L = make_uint4(l[0], l[1], l[2], l[3]);
}
__device__ __forceinline__ void split2(float v0, float v1, uint32_t& hi, uint32_t& lo) {
    __nv_bfloat16 h0 = __float2bfloat16(v0), h1 = __float2bfloat16(v1);
    float l0 = v0 - __bfloat162float(h0), l1 = v1 - __bfloat162float(h1);
    hi = (uint32_t)__bfloat16_as_ushort(h0) | ((uint32_t)__bfloat16_as_ushort(h1) << 16);
    lo = (uint32_t)__bfloat16_as_ushort(__float2bfloat16(l0)) |
         ((uint32_t)__bfloat16_as_ushort(__float2bfloat16(l1)) << 16);
}

// ---------------- kernel A: fold BN, bf16-split, lay out weights ----------------
__global__ void prep_kernel(const float* __restrict__ W1, const float* __restrict__ b1,
                            const float* __restrict__ g1, const float* __restrict__ be1,
                            const float* __restrict__ m1, const float* __restrict__ v1,
                            const float* __restrict__ W2, const float* __restrict__ b2,
                            const float* __restrict__ g2, const float* __restrict__ be2,
                            const float* __restrict__ m2, const float* __restrict__ v2) {
    int idx = blockIdx.x * blockDim.x + threadIdx.x;
    int stride = gridDim.x * blockDim.x;

    for (int g = idx; g < 256 * 48; g += stride) {
        int o = g / 48, k0 = (g % 48) * 8;
        float a = g1[o] * rsqrtf(v1[o] + 1e-5f);
        float vv[8];
#pragma unroll
        for (int j = 0; j < 8; j++) vv[j] = W1[o * CIN + k0 + j] * a;
        uint4 H, L; pack_split8(vv, H, L);
        int chunk = k0 >> 6, kc = k0 & 63;
        size_t off = (size_t)chunk * W1CH + o * (A1S * 2) + kc * 2;
        *(uint4*)(g_W1h + off) = H;
        *(uint4*)(g_W1l + off) = L;
    }
    for (int g = idx; g < 128 * 32; g += stride) {
        int o = g / 32, k0 = (g % 32) * 8;
        float a = g2[o] * rsqrtf(v2[o] + 1e-5f);
        float vv[8];
#pragma unroll
        for (int j = 0; j < 8; j++) vv[j] = W2[o * H1 + k0 + j] * a;
        uint4 H, L; pack_split8(vv, H, L);
        int chunk = k0 >> 6, kc = k0 & 63;
        size_t off = (size_t)chunk * W2CH + o * (A1S * 2) + kc * 2;
        *(uint4*)(g_W2h + off) = H;
        *(uint4*)(g_W2l + off) = L;
    }
    for (int o = idx; o < H1; o += stride) {
        float a = g1[o] * rsqrtf(v1[o] + 1e-5f);
        g_b1f[o] = (b1[o] - m1[o]) * a + be1[o];
    }
    for (int o = idx; o < H2; o += stride) {
        float a = g2[o] * rsqrtf(v2[o] + 1e-5f);
        g_b2f[o] = (b2[o] - m2[o]) * a + be2[o];
    }
}

// ---------------- kernel B: exact 3-NN + interpolation weights ----------------
__global__ void __launch_bounds__(256) nn_kernel(const float* __restrict__ xyz1,
                                                 const float* __restrict__ xyz2) {
    extern __shared__ float4 sc[];
    const int b = blockIdx.y;
    const int n = blockIdx.x * 256 + threadIdx.x;

    const float* x2 = xyz2 + b * SPTS * 3;
    for (int s = threadIdx.x; s < SPTS; s += 256) {
        float x = x2[s * 3 + 0], y = x2[s * 3 + 1], z = x2[s * 3 + 2];
        sc[s] = make_float4(fmaf(x, x, fmaf(y, y, z * z)), -2.f * x, -2.f * y, -2.f * z);
    }
    __syncthreads();

    const float* q = xyz1 + (b * NPTS + n) * 3;
    const float qx = q[0], qy = q[1], qz = q[2];

    const float INF = __int_as_float(0x7f800000);
    float d0 = INF, d1 = INF, d2 = INF;
    int i0 = 0, i1 = 0, i2 = 0;

#pragma unroll 4
    for (int s = 0; s < SPTS; s++) {
        float4 c = sc[s];
        float t = fmaf(c.y, qx, c.x);
        t = fmaf(c.z, qy, t);
        t = fmaf(c.w, qz, t);
        if (t < d2) {
            if (t < d1) {
                d2 = d1; i2 = i1;
                if (t < d0) { d1 = d0; i1 = i0; d0 = t; i0 = s; }
                else        { d1 = t;  i1 = s; }
            } else { d2 = t; i2 = s; }
        }
    }

    const float qn = fmaf(qx, qx, fmaf(qy, qy, qz * qz));
    float r0 = 1.f / ((d0 + qn) + 1e-8f);
    float r1 = 1.f / ((d1 + qn) + 1e-8f);
    float r2 = 1.f / ((d2 + qn) + 1e-8f);
    float inv = 1.f / (r0 + r1 + r2);

    const int base = (b * NPTS + n) * 3;
    g_ni[base + 0] = i0; g_ni[base + 1] = i1; g_ni[base + 2] = i2;
    g_nw[base + 0] = r0 * inv; g_nw[base + 1] = r1 * inv; g_nw[base + 2] = r2 * inv;
}

// ---------------- kernel C: fused interp + MLP via HMMA (mma.sync bf16) ----------------
// 128 points/block, 512 threads (16 warps).
// Phase1 SMEM: A1h@0 (18432) A1l@18432 B1h@36864 (36864) B1l@73728  -> 110592
// Phase2 SMEM: H1h@0 (67584) H1l@67584 B2h@135168 (18432) B2l@153600 -> 172032
#define A1H_OFF 0
#define A1L_OFF 18432
#define B1H_OFF 36864
#define B1L_OFF 73728
#define H1H_OFF 0
#define H1L_OFF 67584
#define B2H_OFF 135168
#define B2L_OFF 153600
#define SMEM_BYTES 172032

__global__ void __launch_bounds__(512, 1) fused_kernel(const float* __restrict__ feat1,
                                                       const float* __restrict__ feat2,
                                                       float* __restrict__ out) {
    extern __shared__ __align__(128) char sm[];
    const uint32_t sb = smem_to_u32(sm);
    const int tid  = threadIdx.x;
    const int lane = tid & 31;
    const int wid  = tid >> 5;
    const int b    = blockIdx.y;
    const int n0g  = blockIdx.x * 128;

    // producer mapping: 4 threads per point row
    const int p = tid >> 2;
    const int q = tid & 3;
    const int nbase = (b * NPTS + n0g + p) * 3;

    // ldmatrix group decomposition
    const int r8 = lane & 7;
    const int g4 = lane >> 3;           // 0..3
    const int gm = (g4 & 1) << 3;       // row +8 selector (A) / k +8 (B)
    const int gk = (g4 >> 1) << 3;

    // GEMM1 warp tile: M32 x N64 over M128 x N256
    const int m0  = (wid >> 2) * 32;
    const int n10 = (wid & 3) * 64;

    float d1[2][8][4];
#pragma unroll
    for (int mt = 0; mt < 2; mt++)
#pragma unroll
        for (int nt = 0; nt < 8; nt++)
#pragma unroll
            for (int i = 0; i < 4; i++) d1[mt][nt][i] = 0.f;

    // A-side ldmatrix byte offsets (k0 added per step)
    const uint32_t a1off = (uint32_t)(m0 + r8 + gm) * (A1S * 2) + gk * 2;
    // B-side: row n10 + np*16 + r8 + gk ; col gm
    const uint32_t b1row = (uint32_t)(n10 + r8 + gk);

    // ================= GEMM1: K = 384 in 6 chunks of 64 =================
    for (int ci = 0; ci < 6; ci++) {
        __syncthreads();   // previous chunk's mma reads done

        // --- produce A chunk (bf16 split) ---
        if (ci < 2) {
            const float4* src = (const float4*)(feat1 + ((size_t)(b * NPTS + n0g + p)) * C1
                                                + ci * 64 + q * 16);
#pragma unroll
            for (int g2 = 0; g2 < 2; g2++) {
                float4 x = __ldg(src + 2 * g2), y = __ldg(src + 2 * g2 + 1);
                float v8[8] = {x.x, x.y, x.z, x.w, y.x, y.y, y.z, y.w};
                uint4 H, L; pack_split8(v8, H, L);
                uint32_t off = (uint32_t)p * (A1S * 2) + (q * 16 + g2 * 8) * 2;
                *(uint4*)(sm + A1H_OFF + off) = H;
                *(uint4*)(sm + A1L_OFF + off) = L;
            }
        } else {
            const int j0 = g_ni[nbase], j1 = g_ni[nbase + 1], j2 = g_ni[nbase + 2];
            const float w0 = g_nw[nbase], w1 = g_nw[nbase + 1], w2 = g_nw[nbase + 2];
            const int c0f = (ci - 2) * 64 + q * 16;
            const float4* r0p = (const float4*)(feat2 + ((size_t)b * SPTS + j0) * C2 + c0f);
            const float4* r1p = (const float4*)(feat2 + ((size_t)b * SPTS + j1) * C2 + c0f);
            const float4* r2p = (const float4*)(feat2 + ((size_t)b * SPTS + j2) * C2 + c0f);
#pragma unroll
            for (int g2 = 0; g2 < 2; g2++) {
                float4 a0 = __ldg(r0p + 2 * g2), a1 = __ldg(r0p + 2 * g2 + 1);
                float4 b0 = __ldg(r1p + 2 * g2), b1v = __ldg(r1p + 2 * g2 + 1);
                float4 c0 = __ldg(r2p + 2 * g2), c1v = __ldg(r2p + 2 * g2 + 1);
                float v8[8];
                v8[0] = fmaf(w0, a0.x, fmaf(w1, b0.x, w2 * c0.x));
                v8[1] = fmaf(w0, a0.y, fmaf(w1, b0.y, w2 * c0.y));
                v8[2] = fmaf(w0, a0.z, fmaf(w1, b0.z, w2 * c0.z));
                v8[3] = fmaf(w0, a0.w, fmaf(w1, b0.w, w2 * c0.w));
                v8[4] = fmaf(w0, a1.x, fmaf(w1, b1v.x, w2 * c1v.x));
                v8[5] = fmaf(w0, a1.y, fmaf(w1, b1v.y, w2 * c1v.y));
                v8[6] = fmaf(w0, a1.z, fmaf(w1, b1v.z, w2 * c1v.z));
                v8[7] = fmaf(w0, a1.w, fmaf(w1, b1v.w, w2 * c1v.w));
                uint4 H, L; pack_split8(v8, H, L);
                uint32_t off = (uint32_t)p * (A1S * 2) + (q * 16 + g2 * 8) * 2;
                *(uint4*)(sm + A1H_OFF + off) = H;
                *(uint4*)(sm + A1L_OFF + off) = L;
            }
        }

        // --- copy W1 chunk (pre-laid-out) ---
        {
            const uint4* srcH = (const uint4*)(g_W1h + (size_t)ci * W1CH);
            const uint4* srcL = (const uint4*)(g_W1l + (size_t)ci * W1CH);
            uint4* dstH = (uint4*)(sm + B1H_OFF);
            uint4* dstL = (uint4*)(sm + B1L_OFF);
#pragma unroll
            for (int i = tid; i < W1CH / 16; i += 512) {
                dstH[i] = __ldg(srcH + i);
                dstL[i] = __ldg(srcL + i);
            }
        }
        __syncthreads();

        // --- consume: 4 k16 steps ---
#pragma unroll
        for (int ks = 0; ks < 4; ks++) {
            uint32_t ah[2][4], al[2][4], bb[8][2];
            const uint32_t ka = a1off + ks * 32;
            ldsm4(ah[0], sb + A1H_OFF + ka);
            ldsm4(ah[1], sb + A1H_OFF + ka + 16 * (A1S * 2));
            ldsm4(al[0], sb + A1L_OFF + ka);
            ldsm4(al[1], sb + A1L_OFF + ka + 16 * (A1S * 2));
#pragma unroll
            for (int np = 0; np < 4; np++)
                ldsm4(&bb[2 * np][0],
                      sb + B1H_OFF + (b1row + np * 16) * (A1S * 2) + (ks * 16 + gm) * 2);
#pragma unroll
            for (int mt = 0; mt < 2; mt++)
#pragma unroll
                for (int nt = 0; nt < 8; nt++) mma_bf16(d1[mt][nt], ah[mt], bb[nt]);
#pragma unroll
            for (int mt = 0; mt < 2; mt++)
#pragma unroll
                for (int nt = 0; nt < 8; nt++) mma_bf16(d1[mt][nt], al[mt], bb[nt]);
#pragma unroll
            for (int np = 0; np < 4; np++)
                ldsm4(&bb[2 * np][0],
                      sb + B1L_OFF + (b1row + np * 16) * (A1S * 2) + (ks * 16 + gm) * 2);
#pragma unroll
            for (int mt = 0; mt < 2; mt++)
#pragma unroll
                for (int nt = 0; nt < 8; nt++) mma_bf16(d1[mt][nt], ah[mt], bb[nt]);
        }
    }
    __syncthreads();   // all GEMM1 smem reads done before h1 overwrite

    // ============ epilogue1: bias + ReLU + bf16-split -> h1 SMEM ============
#pragma unroll
    for (int nt = 0; nt < 8; nt++) {
        const int col = n10 + nt * 8 + (lane & 3) * 2;
        const float bb0 = g_b1f[col], bb1 = g_b1f[col + 1];
#pragma unroll
        for (int mt = 0; mt < 2; mt++) {
            const int row = m0 + mt * 16 + (lane >> 2);
            const float* dd = d1[mt][nt];
            uint32_t hi, lo;
            split2(fmaxf(dd[0] + bb0, 0.f), fmaxf(dd[1] + bb1, 0.f), hi, lo);
            *(uint32_t*)(sm + H1H_OFF + row * (H1S * 2) + col * 2) = hi;
            *(uint32_t*)(sm + H1L_OFF + row * (H1S * 2) + col * 2) = lo;
            split2(fmaxf(dd[2] + bb0, 0.f), fmaxf(dd[3] + bb1, 0.f), hi, lo);
            *(uint32_t*)(sm + H1H_OFF + (row + 8) * (H1S * 2) + col * 2) = hi;
            *(uint32_t*)(sm + H1L_OFF + (row + 8) * (H1S * 2) + col * 2) = lo;
        }
    }

    // ================= GEMM2: h1[128][256] x W2^T -> out[128][128] =================
    const int n20 = (wid & 3) * 32;
    float d2[2][4][4];
#pragma unroll
    for (int mt = 0; mt < 2; mt++)
#pragma unroll
        for (int nt = 0; nt < 4; nt++)
#pragma unroll
            for (int i = 0; i < 4; i++) d2[mt][nt][i] = 0.f;

    const uint32_t a2row = (uint32_t)(m0 + r8 + gm);
    const uint32_t b2row = (uint32_t)(n20 + r8 + gk);

    for (int cj = 0; cj < 4; cj++) {
        __syncthreads();   // h1 writes done (cj=0) / previous chunk mma done
        {
            const uint4* srcH = (const uint4*)(g_W2h + (size_t)cj * W2CH);
            const uint4* srcL = (const uint4*)(g_W2l + (size_t)cj * W2CH);
            uint4* dstH = (uint4*)(sm + B2H_OFF);
            uint4* dstL = (uint4*)(sm + B2L_OFF);
#pragma unroll
            for (int i = tid; i < W2CH / 16; i += 512) {
                dstH[i] = __ldg(srcH + i);
                dstL[i] = __ldg(srcL + i);
            }
        }
        __syncthreads();

#pragma unroll
        for (int ks = 0; ks < 4; ks++) {
            uint32_t ah[2][4], al[2][4], bb[4][2];
            const int kg = cj * 64 + ks * 16;
            const uint32_t ka = a2row * (H1S * 2) + (kg + gk) * 2;
            ldsm4(ah[0], sb + H1H_OFF + ka);
            ldsm4(ah[1], sb + H1H_OFF + ka + 16 * (H1S * 2));
            ldsm4(al[0], sb + H1L_OFF + ka);
            ldsm4(al[1], sb + H1L_OFF + ka + 16 * (H1S * 2));
#pragma unroll
            for (int np = 0; np < 2; np++)
                ldsm4(&bb[2 * np][0],
                      sb + B2H_OFF + (b2row + np * 16) * (A1S * 2) + (ks * 16 + gm) * 2);
#pragma unroll
            for (int mt = 0; mt < 2; mt++)
#pragma unroll
                for (int nt = 0; nt < 4; nt++) mma_bf16(d2[mt][nt], ah[mt], bb[nt]);
#pragma unroll
            for (int mt = 0; mt < 2; mt++)
#pragma unroll
                for (int nt = 0; nt < 4; nt++) mma_bf16(d2[mt][nt], al[mt], bb[nt]);
#pragma unroll
            for (int np = 0; np < 2; np++)
                ldsm4(&bb[2 * np][0],
                      sb + B2L_OFF + (b2row + np * 16) * (A1S * 2) + (ks * 16 + gm) * 2);
#pragma unroll
            for (int mt = 0; mt < 2; mt++)
#pragma unroll
                for (int nt = 0; nt < 4; nt++) mma_bf16(d2[mt][nt], ah[mt], bb[nt]);
        }
    }

    // ============ epilogue2: bias + ReLU -> fp32 out ============
#pragma unroll
    for (int nt = 0; nt < 4; nt++) {
        const int col = n20 + nt * 8 + (lane & 3) * 2;
        const float bb0 = g_b2f[col], bb1 = g_b2f[col + 1];
#pragma unroll
        for (int mt = 0; mt < 2; mt++) {
            const int row = m0 + mt * 16 + (lane >> 2);
            const float* dd = d2[mt][nt];
            float2 v0 = make_float2(fmaxf(dd[0] + bb0, 0.f), fmaxf(dd[1] + bb1, 0.f));
            float2 v1 = make_float2(fmaxf(dd[2] + bb0, 0.f), fmaxf(dd[3] + bb1, 0.f));
            *(float2*)(out + ((size_t)(b * NPTS + n0g + row)) * H2 + col) = v0;
            *(float2*)(out + ((size_t)(b * NPTS + n0g + row + 8)) * H2 + col) = v1;
        }
    }
}

// ---------------- launch ----------------
extern "C" void kernel_launch(void* const* d_in, const int* in_sizes, int n_in,
                              void* d_out, int out_size) {
    const float* xyz1  = (const float*)d_in[0];
    const float* feat1 = (const float*)d_in[1];
    const float* xyz2  = (const float*)d_in[2];
    const float* feat2 = (const float*)d_in[3];
    const float* W1  = (const float*)d_in[4];
    const float* b1  = (const float*)d_in[5];
    const float* g1  = (const float*)d_in[6];
    const float* be1 = (const float*)d_in[7];
    const float* m1  = (const float*)d_in[8];
    const float* v1  = (const float*)d_in[9];
    const float* W2  = (const float*)d_in[10];
    const float* b2  = (const float*)d_in[11];
    const float* g2  = (const float*)d_in[12];
    const float* be2 = (const float*)d_in[13];
    const float* m2  = (const float*)d_in[14];
    const float* v2  = (const float*)d_in[15];
    float* out = (float*)d_out;

    cudaFuncSetAttribute(nn_kernel, cudaFuncAttributeMaxDynamicSharedMemorySize,
                         SPTS * (int)sizeof(float4));
    cudaFuncSetAttribute(fused_kernel, cudaFuncAttributeMaxDynamicSharedMemorySize,
                         SMEM_BYTES);

    prep_kernel<<<64, 256>>>(W1, b1, g1, be1, m1, v1, W2, b2, g2, be2, m2, v2);
    nn_kernel<<<dim3(NPTS / 256, BB), 256, SPTS * sizeof(float4)>>>(xyz1, xyz2);
    fused_kernel<<<dim3(NPTS / 128, BB), 512, SMEM_BYTES>>>(feat1, feat2, out);
}

// round 6
// speedup vs baseline: 2.4257x; 1.1602x over previous
#include <cuda_runtime.h>
#include <cuda_bf16.h>
#include <cstdint>

// Problem constants
#define BB   4
#define NPTS 16384
#define SPTS 4096
#define C1   128
#define C2   256
#define CIN  384
#define H1   256
#define H2   128

#define NPB  64          // points per fused block
#define NTHR 256

// Tile row strides: A/B chunk rows = 32 bf16 + 8 pad = 40 bf16 = 80B
// (80B = 5 16B-granules, 5 coprime 8 -> conflict-free ldmatrix)
// H1 rows = 256 bf16 + 8 pad = 264 bf16 = 528B (33 granules, coprime 8)
#define CHS  80
#define H1SB 528

// Weight chunk sizes (one k32 chunk, hi or lo): W1: 256 rows x 80B = 20480
//                                               W2: 128 rows x 80B = 10240
#define W1CB 20480
#define W2CB 10240

__device__ __align__(16) unsigned char g_W1h[12 * W1CB];
__device__ __align__(16) unsigned char g_W1l[12 * W1CB];
__device__ __align__(16) unsigned char g_W2h[8 * W2CB];
__device__ __align__(16) unsigned char g_W2l[8 * W2CB];
__device__ float g_b1f[H1];
__device__ float g_b2f[H2];
__device__ int   g_ni[BB * NPTS * 3];
__device__ float g_nw[BB * NPTS * 3];

// ---------------- helpers ----------------
__device__ __forceinline__ uint32_t smem_to_u32(const void* p) {
    uint32_t a;
    asm("{ .reg .u64 t; cvta.to.shared.u64 t, %1; cvt.u32.u64 %0, t; }" : "=r"(a) : "l"(p));
    return a;
}
__device__ __forceinline__ void ldsm4(uint32_t* r, uint32_t a) {
    asm volatile("ldmatrix.sync.aligned.m8n8.x4.shared.b16 {%0,%1,%2,%3}, [%4];"
                 : "=r"(r[0]), "=r"(r[1]), "=r"(r[2]), "=r"(r[3]) : "r"(a));
}
__device__ __forceinline__ void mma_bf16(float* d, const uint32_t* a, const uint32_t* b) {
    asm volatile("mma.sync.aligned.m16n8k16.row.col.f32.bf16.bf16.f32 "
                 "{%0,%1,%2,%3}, {%4,%5,%6,%7}, {%8,%9}, {%0,%1,%2,%3};"
                 : "+f"(d[0]), "+f"(d[1]), "+f"(d[2]), "+f"(d[3])
                 : "r"(a[0]), "r"(a[1]), "r"(a[2]), "r"(a[3]), "r"(b[0]), "r"(b[1]));
}
__device__ __forceinline__ void cpa16(uint32_t dst, const void* src) {
    asm volatile("cp.async.cg.shared.global [%0], [%1], 16;" :: "r"(dst), "l"(src));
}
#define CP_COMMIT() asm volatile("cp.async.commit_group;" ::: "memory")
#define CP_WAIT0()  asm volatile("cp.async.wait_group 0;" ::: "memory")

__device__ __forceinline__ void pack_split4(const float* v, uint2& H, uint2& L) {
    unsigned int h[2], l[2];
#pragma unroll
    for (int j = 0; j < 2; j++) {
        __nv_bfloat16 h0 = __float2bfloat16(v[2 * j]);
        __nv_bfloat16 h1 = __float2bfloat16(v[2 * j + 1]);
        float l0 = v[2 * j]     - __bfloat162float(h0);
        float l1 = v[2 * j + 1] - __bfloat162float(h1);
        h[j] = (unsigned int)__bfloat16_as_ushort(h0) |
               ((unsigned int)__bfloat16_as_ushort(h1) << 16);
        l[j] = (unsigned int)__bfloat16_as_ushort(__float2bfloat16(l0)) |
               ((unsigned int)__bfloat16_as_ushort(__float2bfloat16(l1)) << 16);
    }
    H = make_uint2(h[0], h[1]);
    L = make_uint2(l[0], l[1]);
}
__device__ __forceinline__ void split2(float v0, float v1, uint32_t& hi, uint32_t& lo) {
    __nv_bfloat16 h0 = __float2bfloat16(v0), h1 = __float2bfloat16(v1);
    float l0 = v0 - __bfloat162float(h0), l1 = v1 - __bfloat162float(h1);
    hi = (uint32_t)__bfloat16_as_ushort(h0) | ((uint32_t)__bfloat16_as_ushort(h1) << 16);
    lo = (uint32_t)__bfloat16_as_ushort(__float2bfloat16(l0)) |
         ((uint32_t)__bfloat16_as_ushort(__float2bfloat16(l1)) << 16);
}

// ---------------- kernel A: fold BN, bf16-split, lay out weights (k32 chunks) --------
__global__ void prep_kernel(const float* __restrict__ W1, const float* __restrict__ b1,
                            const float* __restrict__ g1, const float* __restrict__ be1,
                            const float* __restrict__ m1, const float* __restrict__ v1,
                            const float* __restrict__ W2, const float* __restrict__ b2,
                            const float* __restrict__ g2, const float* __restrict__ be2,
                            const float* __restrict__ m2, const float* __restrict__ v2) {
    int idx = blockIdx.x * blockDim.x + threadIdx.x;
    int stride = gridDim.x * blockDim.x;

    for (int g = idx; g < 256 * 96; g += stride) {          // 4-wide groups
        int o = g / 96, k0 = (g % 96) * 4;
        float a = g1[o] * rsqrtf(v1[o] + 1e-5f);
        float vv[4];
#pragma unroll
        for (int j = 0; j < 4; j++) vv[j] = W1[o * CIN + k0 + j] * a;
        uint2 H, L; pack_split4(vv, H, L);
        int chunk = k0 >> 5, kc = k0 & 31;
        size_t off = (size_t)chunk * W1CB + o * CHS + kc * 2;
        *(uint2*)(g_W1h + off) = H;
        *(uint2*)(g_W1l + off) = L;
    }
    for (int g = idx; g < 128 * 64; g += stride) {
        int o = g / 64, k0 = (g % 64) * 4;
        float a = g2[o] * rsqrtf(v2[o] + 1e-5f);
        float vv[4];
#pragma unroll
        for (int j = 0; j < 4; j++) vv[j] = W2[o * H1 + k0 + j] * a;
        uint2 H, L; pack_split4(vv, H, L);
        int chunk = k0 >> 5, kc = k0 & 31;
        size_t off = (size_t)chunk * W2CB + o * CHS + kc * 2;
        *(uint2*)(g_W2h + off) = H;
        *(uint2*)(g_W2l + off) = L;
    }
    for (int o = idx; o < H1; o += stride) {
        float a = g1[o] * rsqrtf(v1[o] + 1e-5f);
        g_b1f[o] = (b1[o] - m1[o]) * a + be1[o];
    }
    for (int o = idx; o < H2; o += stride) {
        float a = g2[o] * rsqrtf(v2[o] + 1e-5f);
        g_b2f[o] = (b2[o] - m2[o]) * a + be2[o];
    }
}

// ---------------- kernel B: exact 3-NN + interpolation weights (unchanged) ----------
__global__ void __launch_bounds__(256) nn_kernel(const float* __restrict__ xyz1,
                                                 const float* __restrict__ xyz2) {
    extern __shared__ float4 sc[];
    const int b = blockIdx.y;
    const int n = blockIdx.x * 256 + threadIdx.x;

    const float* x2 = xyz2 + b * SPTS * 3;
    for (int s = threadIdx.x; s < SPTS; s += 256) {
        float x = x2[s * 3 + 0], y = x2[s * 3 + 1], z = x2[s * 3 + 2];
        sc[s] = make_float4(fmaf(x, x, fmaf(y, y, z * z)), -2.f * x, -2.f * y, -2.f * z);
    }
    __syncthreads();

    const float* qq = xyz1 + (b * NPTS + n) * 3;
    const float qx = qq[0], qy = qq[1], qz = qq[2];

    const float INF = __int_as_float(0x7f800000);
    float d0 = INF, d1 = INF, d2 = INF;
    int i0 = 0, i1 = 0, i2 = 0;

#pragma unroll 4
    for (int s = 0; s < SPTS; s++) {
        float4 c = sc[s];
        float t = fmaf(c.y, qx, c.x);
        t = fmaf(c.z, qy, t);
        t = fmaf(c.w, qz, t);
        if (t < d2) {
            if (t < d1) {
                d2 = d1; i2 = i1;
                if (t < d0) { d1 = d0; i1 = i0; d0 = t; i0 = s; }
                else        { d1 = t;  i1 = s; }
            } else { d2 = t; i2 = s; }
        }
    }

    const float qn = fmaf(qx, qx, fmaf(qy, qy, qz * qz));
    float r0 = 1.f / ((d0 + qn) + 1e-8f);
    float r1 = 1.f / ((d1 + qn) + 1e-8f);
    float r2 = 1.f / ((d2 + qn) + 1e-8f);
    float inv = 1.f / (r0 + r1 + r2);

    const int base = (b * NPTS + n) * 3;
    g_ni[base + 0] = i0; g_ni[base + 1] = i1; g_ni[base + 2] = i2;
    g_nw[base + 0] = r0 * inv; g_nw[base + 1] = r1 * inv; g_nw[base + 2] = r2 * inv;
}

// ---------------- kernel C: pipelined fused interp + MLP via HMMA ----------------
// 64 points/block, 256 threads (8 warps), 2 blocks/SM.
// SMEM (bytes):
//  phase1: A1 bufs 2 x (hi 5120 | lo 5120) @0          .. 20480
//          B1 bufs 2 x (hi 20480 | lo 20480) @20480    .. 102400
//  phase2: H1 hi @0 (33792) | lo @33792 (33792)        .. 67584
//          B2 bufs 2 x (hi 10240 | lo 10240) @67584    .. 108544
#define A1_OFF  0
#define A1_BUF  10240
#define A1_LO   5120
#define B1_OFF  20480
#define B1_BUF  40960
#define B1_LO   20480
#define H1H_OFF 0
#define H1L_OFF 33792
#define B2_OFF  67584
#define B2_BUF  20480
#define B2_LO   10240
#define SMEM_BYTES 108544

__global__ void __launch_bounds__(NTHR, 2) fused_kernel(const float* __restrict__ feat1,
                                                        const float* __restrict__ feat2,
                                                        float* __restrict__ out) {
    extern __shared__ __align__(128) char sm[];
    const uint32_t sb = smem_to_u32(sm);
    const int tid  = threadIdx.x;
    const int lane = tid & 31;
    const int wid  = tid >> 5;
    const int b    = blockIdx.y;
    const int n0g  = blockIdx.x * NPB;

    // producer mapping: 4 threads per point
    const int p = tid >> 2;
    const int q = tid & 3;
    const int nbase = (b * NPTS + n0g + p) * 3;
    const int j0 = g_ni[nbase], j1 = g_ni[nbase + 1], j2 = g_ni[nbase + 2];
    const float w0 = g_nw[nbase], w1 = g_nw[nbase + 1], w2 = g_nw[nbase + 2];

    // ldmatrix decomposition
    const int r8 = lane & 7;
    const int g4 = lane >> 3;
    const int gm = (g4 & 1) << 3;
    const int gk = (g4 >> 1) << 3;

    // warp tiles: GEMM1 M16xN128, GEMM2 M16xN64
    const int m0  = (wid >> 1) * 16;
    const int nh0 = (wid & 1) * 128;
    const int n20 = (wid & 1) * 64;

    float d1[16][4];
#pragma unroll
    for (int nt = 0; nt < 16; nt++)
#pragma unroll
        for (int i = 0; i < 4; i++) d1[nt][i] = 0.f;

    float4 pf0, pf1, pf2;

    auto ldg_part = [&](int nc, int h) {
        const int cl = q * 8 + h * 4;
        if (nc < 4) {
            pf0 = __ldg((const float4*)(feat1 + ((size_t)(b * NPTS + n0g + p)) * C1
                                        + nc * 32 + cl));
        } else {
            const int c2 = (nc - 4) * 32 + cl;
            pf0 = __ldg((const float4*)(feat2 + ((size_t)b * SPTS + j0) * C2 + c2));
            pf1 = __ldg((const float4*)(feat2 + ((size_t)b * SPTS + j1) * C2 + c2));
            pf2 = __ldg((const float4*)(feat2 + ((size_t)b * SPTS + j2) * C2 + c2));
        }
    };
    auto sts_part = [&](int nc, int h) {
        float v[4];
        if (nc < 4) {
            v[0] = pf0.x; v[1] = pf0.y; v[2] = pf0.z; v[3] = pf0.w;
        } else {
            v[0] = fmaf(w0, pf0.x, fmaf(w1, pf1.x, w2 * pf2.x));
            v[1] = fmaf(w0, pf0.y, fmaf(w1, pf1.y, w2 * pf2.y));
            v[2] = fmaf(w0, pf0.z, fmaf(w1, pf1.z, w2 * pf2.z));
            v[3] = fmaf(w0, pf0.w, fmaf(w1, pf1.w, w2 * pf2.w));
        }
        uint2 H, L; pack_split4(v, H, L);
        char* dst = sm + A1_OFF + (nc & 1) * A1_BUF + p * CHS + (q * 8 + h * 4) * 2;
        *(uint2*)dst = H;
        *(uint2*)(dst + A1_LO) = L;
    };
    auto consume1 = [&](uint32_t Au, uint32_t Bu, int ks) {
        uint32_t ah[4], al[4];
        const uint32_t aad = Au + (uint32_t)((m0 + r8 + gm) * CHS + (ks * 16 + gk) * 2);
        ldsm4(ah, aad);
        ldsm4(al, aad + A1_LO);
#pragma unroll
        for (int nb = 0; nb < 2; nb++) {
            uint32_t bbf[8][2];
#pragma unroll
            for (int np = 0; np < 4; np++)
                ldsm4(&bbf[2 * np][0],
                      Bu + (uint32_t)((nh0 + nb * 64 + np * 16 + r8 + gk) * CHS
                                      + (ks * 16 + gm) * 2));
#pragma unroll
            for (int nt = 0; nt < 8; nt++) mma_bf16(d1[nb * 8 + nt], ah, bbf[nt]);
#pragma unroll
            for (int nt = 0; nt < 8; nt++) mma_bf16(d1[nb * 8 + nt], al, bbf[nt]);
#pragma unroll
            for (int np = 0; np < 4; np++)
                ldsm4(&bbf[2 * np][0],
                      Bu + B1_LO + (uint32_t)((nh0 + nb * 64 + np * 16 + r8 + gk) * CHS
                                              + (ks * 16 + gm) * 2));
#pragma unroll
            for (int nt = 0; nt < 8; nt++) mma_bf16(d1[nb * 8 + nt], ah, bbf[nt]);
        }
    };

    // ---- pre-loop: produce chunk 0 + cp.async W1 chunk 0 ----
    ldg_part(0, 0); sts_part(0, 0);
    ldg_part(0, 1); sts_part(0, 1);
    {
        const unsigned char* srcH = g_W1h;
        const unsigned char* srcL = g_W1l;
        const uint32_t dH = sb + B1_OFF;
        for (int i = tid * 16; i < W1CB; i += NTHR * 16) {
            cpa16(dH + i, srcH + i);
            cpa16(dH + B1_LO + i, srcL + i);
        }
        CP_COMMIT();
    }

    // ---- phase 1: 12 chunks of k32 ----
    for (int ci = 0; ci < 12; ci++) {
        const int s = ci & 1;
        const uint32_t Au = sb + A1_OFF + s * A1_BUF;
        const uint32_t Bu = sb + B1_OFF + s * B1_BUF;
        const int nc = ci + 1;

        CP_WAIT0();          // W1(ci) arrived (thread-local)
        __syncthreads();     // all threads: W1(ci)/A(ci) visible; consume(ci-1) done

        if (nc < 12) {       // prefetch weights for next chunk (covered by this mma phase)
            const unsigned char* srcH = g_W1h + (size_t)nc * W1CB;
            const unsigned char* srcL = g_W1l + (size_t)nc * W1CB;
            const uint32_t dH = sb + B1_OFF + (nc & 1) * B1_BUF;
            for (int i = tid * 16; i < W1CB; i += NTHR * 16) {
                cpa16(dH + i, srcH + i);
                cpa16(dH + B1_LO + i, srcL + i);
            }
            CP_COMMIT();
        }

        if (nc < 12) ldg_part(nc, 0);
        consume1(Au, Bu, 0);
        if (nc < 12) { sts_part(nc, 0); ldg_part(nc, 1); }
        consume1(Au, Bu, 1);
        if (nc < 12) sts_part(nc, 1);
    }
    __syncthreads();         // all consumes done before H1/B2 region overwrite

    // ---- prefetch W2 chunk 0, then epilogue1 (covers the cp.async) ----
    {
        const uint32_t dH = sb + B2_OFF;
        for (int i = tid * 16; i < W2CB; i += NTHR * 16) {
            cpa16(dH + i, g_W2h + i);
            cpa16(dH + B2_LO + i, g_W2l + i);
        }
        CP_COMMIT();
    }
    // epilogue1: bias + ReLU + bf16 split -> H1 smem
#pragma unroll
    for (int nt = 0; nt < 16; nt++) {
        const int col = nh0 + nt * 8 + (lane & 3) * 2;
        const float bb0 = __ldg(g_b1f + col), bb1 = __ldg(g_b1f + col + 1);
        const int row = m0 + (lane >> 2);
        uint32_t hi, lo;
        split2(fmaxf(d1[nt][0] + bb0, 0.f), fmaxf(d1[nt][1] + bb1, 0.f), hi, lo);
        *(uint32_t*)(sm + H1H_OFF + row * H1SB + col * 2) = hi;
        *(uint32_t*)(sm + H1L_OFF + row * H1SB + col * 2) = lo;
        split2(fmaxf(d1[nt][2] + bb0, 0.f), fmaxf(d1[nt][3] + bb1, 0.f), hi, lo);
        *(uint32_t*)(sm + H1H_OFF + (row + 8) * H1SB + col * 2) = hi;
        *(uint32_t*)(sm + H1L_OFF + (row + 8) * H1SB + col * 2) = lo;
    }

    // ---- phase 2: GEMM2, 8 chunks of k32 ----
    float d2[8][4];
#pragma unroll
    for (int nt = 0; nt < 8; nt++)
#pragma unroll
        for (int i = 0; i < 4; i++) d2[nt][i] = 0.f;

    for (int cj = 0; cj < 8; cj++) {
        const int s = cj & 1;
        const uint32_t Bu = sb + B2_OFF + s * B2_BUF;
        const int ncj = cj + 1;

        CP_WAIT0();          // W2(cj) arrived
        __syncthreads();     // also orders H1 writes (cj==0) and buffer reuse

        if (ncj < 8) {
            const unsigned char* srcH = g_W2h + (size_t)ncj * W2CB;
            const unsigned char* srcL = g_W2l + (size_t)ncj * W2CB;
            const uint32_t dH = sb + B2_OFF + (ncj & 1) * B2_BUF;
            for (int i = tid * 16; i < W2CB; i += NTHR * 16) {
                cpa16(dH + i, srcH + i);
                cpa16(dH + B2_LO + i, srcL + i);
            }
            CP_COMMIT();
        }

#pragma unroll
        for (int ks = 0; ks < 2; ks++) {
            uint32_t ah[4], al[4];
            const uint32_t aad = sb + (uint32_t)((m0 + r8 + gm) * H1SB
                                                 + (cj * 32 + ks * 16 + gk) * 2);
            ldsm4(ah, aad + H1H_OFF);
            ldsm4(al, aad + H1L_OFF);
            uint32_t bbf[8][2];
#pragma unroll
            for (int np = 0; np < 4; np++)
                ldsm4(&bbf[2 * np][0],
                      Bu + (uint32_t)((n20 + np * 16 + r8 + gk) * CHS + (ks * 16 + gm) * 2));
#pragma unroll
            for (int nt = 0; nt < 8; nt++) mma_bf16(d2[nt], ah, bbf[nt]);
#pragma unroll
            for (int nt = 0; nt < 8; nt++) mma_bf16(d2[nt], al, bbf[nt]);
#pragma unroll
            for (int np = 0; np < 4; np++)
                ldsm4(&bbf[2 * np][0],
                      Bu + B2_LO + (uint32_t)((n20 + np * 16 + r8 + gk) * CHS
                                              + (ks * 16 + gm) * 2));
#pragma unroll
            for (int nt = 0; nt < 8; nt++) mma_bf16(d2[nt], ah, bbf[nt]);
        }
    }

    // ---- epilogue2: bias + ReLU -> fp32 out ----
#pragma unroll
    for (int nt = 0; nt < 8; nt++) {
        const int col = n20 + nt * 8 + (lane & 3) * 2;
        const float bb0 = __ldg(g_b2f + col), bb1 = __ldg(g_b2f + col + 1);
        const int row = m0 + (lane >> 2);
        float2 v0 = make_float2(fmaxf(d2[nt][0] + bb0, 0.f), fmaxf(d2[nt][1] + bb1, 0.f));
        float2 v1 = make_float2(fmaxf(d2[nt][2] + bb0, 0.f), fmaxf(d2[nt][3] + bb1, 0.f));
        *(float2*)(out + ((size_t)(b * NPTS + n0g + row)) * H2 + col) = v0;
        *(float2*)(out + ((size_t)(b * NPTS + n0g + row + 8)) * H2 + col) = v1;
    }
}

// ---------------- launch ----------------
extern "C" void kernel_launch(void* const* d_in, const int* in_sizes, int n_in,
                              void* d_out, int out_size) {
    const float* xyz1  = (const float*)d_in[0];
    const float* feat1 = (const float*)d_in[1];
    const float* xyz2  = (const float*)d_in[2];
    const float* feat2 = (const float*)d_in[3];
    const float* W1  = (const float*)d_in[4];
    const float* b1  = (const float*)d_in[5];
    const float* g1  = (const float*)d_in[6];
    const float* be1 = (const float*)d_in[7];
    const float* m1  = (const float*)d_in[8];
    const float* v1  = (const float*)d_in[9];
    const float* W2  = (const float*)d_in[10];
    const float* b2  = (const float*)d_in[11];
    const float* g2  = (const float*)d_in[12];
    const float* be2 = (const float*)d_in[13];
    const float* m2  = (const float*)d_in[14];
    const float* v2  = (const float*)d_in[15];
    float* out = (float*)d_out;

    cudaFuncSetAttribute(nn_kernel, cudaFuncAttributeMaxDynamicSharedMemorySize,
                         SPTS * (int)sizeof(float4));
    cudaFuncSetAttribute(fused_kernel, cudaFuncAttributeMaxDynamicSharedMemorySize,
                         SMEM_BYTES);

    prep_kernel<<<64, 256>>>(W1, b1, g1, be1, m1, v1, W2, b2, g2, be2, m2, v2);
    nn_kernel<<<dim3(NPTS / 256, BB), 256, SPTS * sizeof(float4)>>>(xyz1, xyz2);
    fused_kernel<<<dim3(NPTS / NPB, BB), NTHR, SMEM_BYTES>>>(feat1, feat2, out);
}